// round 12
// baseline (speedup 1.0000x reference)
#include <cuda_runtime.h>

#define N_PTS 65536
#define N_NODES 4096
#define KCH 24            // sweep chain length (guard band over 20)
#define KSD 20            // seed chain length
#define IN_STRIDE 35
#define NBINS 4096
#define CHUNK 2048
#define SEEDW 64
#define FINF 3.0e38f

__device__ float4 g_nodes4s[N_NODES];     // Morton-sorted: (vx,vy,vz,|v|^2)
__device__ float4 g_rec_s[N_NODES * 4];   // sorted records: R, g+t, g
__device__ int g_binCount[NBINS], g_binCursor[NBINS], g_cellArr[N_PTS], g_perm[N_PTS];
__device__ int g_nBinCount[NBINS], g_nBinCursor[NBINS], g_nodeStart[NBINS];
__device__ int g_nCell[N_NODES], g_nPerm[N_NODES];

__device__ __forceinline__ unsigned expand3(unsigned v) {
    return (v & 1u) | ((v & 2u) << 2) | ((v & 4u) << 4) | ((v & 8u) << 6);
}
__device__ __forceinline__ int quant4(float x) {
    int q = (int)floorf((x + 3.0f) * (16.0f / 6.0f));
    return q < 0 ? 0 : (q > 15 ? 15 : q);
}
__device__ __forceinline__ unsigned morton3(float x, float y, float z) {
    return expand3(quant4(x)) | (expand3(quant4(y)) << 1) | (expand3(quant4(z)) << 2);
}

__global__ void zero_kernel() {
    int i = blockIdx.x * blockDim.x + threadIdx.x;
    if (i < NBINS) { g_binCount[i] = 0; g_nBinCount[i] = 0; }
}

__global__ void count_kernel(const float* __restrict__ inputs, const float* __restrict__ vd) {
    int idx = blockIdx.x * blockDim.x + threadIdx.x;
    if (idx < N_PTS) {
        const float* pr = inputs + (long)idx * IN_STRIDE;
        unsigned code = morton3(pr[0], pr[1], pr[2]);
        g_cellArr[idx] = (int)code;
        atomicAdd(&g_binCount[code], 1);
    }
    if (idx < N_NODES) {
        unsigned code = morton3(vd[idx*3+0], vd[idx*3+1], vd[idx*3+2]);
        g_nCell[idx] = (int)code;
        atomicAdd(&g_nBinCount[code], 1);
    }
}

// grid = 2 blocks of 1024: block 0 scans point bins, block 1 scans node bins.
__global__ void scan_kernel() {
    __shared__ int ssum[1024];
    int tid = threadIdx.x;
    const int* cntArr = (blockIdx.x == 0) ? g_binCount : g_nBinCount;
    int base = tid * 4;
    int c0 = cntArr[base], c1 = cntArr[base+1], c2 = cntArr[base+2], c3 = cntArr[base+3];
    ssum[tid] = c0 + c1 + c2 + c3;
    __syncthreads();
    for (int off = 1; off < 1024; off <<= 1) {
        int v = ssum[tid];
        int add = (tid >= off) ? ssum[tid - off] : 0;
        __syncthreads();
        ssum[tid] = v + add;
        __syncthreads();
    }
    int excl = (tid > 0) ? ssum[tid - 1] : 0;
    int e0 = excl, e1 = excl + c0, e2 = excl + c0 + c1, e3 = excl + c0 + c1 + c2;
    if (blockIdx.x == 0) {
        g_binCursor[base] = e0; g_binCursor[base+1] = e1;
        g_binCursor[base+2] = e2; g_binCursor[base+3] = e3;
    } else {
        g_nBinCursor[base] = e0; g_nBinCursor[base+1] = e1;
        g_nBinCursor[base+2] = e2; g_nBinCursor[base+3] = e3;
        g_nodeStart[base] = e0; g_nodeStart[base+1] = e1;
        g_nodeStart[base+2] = e2; g_nodeStart[base+3] = e3;
    }
}

__global__ void scatter_kernel() {
    int idx = blockIdx.x * blockDim.x + threadIdx.x;
    if (idx < N_PTS) {
        int pos = atomicAdd(&g_binCursor[g_cellArr[idx]], 1);
        g_perm[pos] = idx;
    }
    if (idx < N_NODES) {
        int pos = atomicAdd(&g_nBinCursor[g_nCell[idx]], 1);
        g_nPerm[pos] = idx;
    }
}

__global__ void build_sorted_kernel(const float* __restrict__ vd, const float* __restrict__ R,
                                    const float* __restrict__ g, const float* __restrict__ t) {
    int pos = blockIdx.x * blockDim.x + threadIdx.x;
    if (pos >= N_NODES) return;
    int j = g_nPerm[pos];
    float vx = vd[j*3+0], vy = vd[j*3+1], vz = vd[j*3+2];
    g_nodes4s[pos] = make_float4(vx, vy, vz, fmaf(vx,vx,fmaf(vy,vy,vz*vz)));
    const float* Rj = R + j*9;
    float g0 = g[j*3+0], g1 = g[j*3+1], g2 = g[j*3+2];
    float gt0 = g0 + t[j*3+0], gt1 = g1 + t[j*3+1], gt2 = g2 + t[j*3+2];
    g_rec_s[pos*4+0] = make_float4(Rj[0], Rj[1], Rj[2], Rj[3]);
    g_rec_s[pos*4+1] = make_float4(Rj[4], Rj[5], Rj[6], Rj[7]);
    g_rec_s[pos*4+2] = make_float4(Rj[8], gt0, gt1, gt2);
    g_rec_s[pos*4+3] = make_float4(g0, g1, g2, 0.0f);
}

// packed key: high 20 bits of float s | 12-bit node index
__device__ __forceinline__ float pack_key(float s, int j) {
    return __uint_as_float((__float_as_uint(s) & 0xFFFFF000u) | (unsigned)j);
}

#define INSERT24(SV) do {                                              \
    _Pragma("unroll")                                                  \
    for (int _k = KCH-1; _k >= 1; --_k)                                \
        d[_k] = fminf(d[_k], fmaxf(d[_k-1], (SV)));                    \
    d[0] = fminf(d[0], (SV));                                          \
} while (0)

#define INSERT20(SV) do {                                              \
    _Pragma("unroll")                                                  \
    for (int _k = KSD-1; _k >= 1; --_k)                                \
        ds[_k] = fminf(ds[_k], fmaxf(ds[_k-1], (SV)));                 \
    ds[0] = fminf(ds[0], (SV));                                        \
} while (0)

__global__ void __launch_bounds__(128) dg_kernel(const float* __restrict__ inputs,
                                                 float* __restrict__ out) {
    __shared__ float4 sn[CHUNK];   // 32 KB

    const int tid = threadIdx.x;
    const int pt = g_perm[blockIdx.x * 128 + tid];
    const float* pr = inputs + (long)pt * IN_STRIDE;
    const float px = pr[0], py = pr[1], pz = pr[2];
    const float pp = fmaf(px, px, fmaf(py, py, pz * pz));
    const float qa = -2.0f * px, qb = -2.0f * py, qc = -2.0f * pz;

    // ---- per-lane seed: unconditional 20-chain over own 64-node Morton window ----
    float ds[KSD];
    #pragma unroll
    for (int k = 0; k < KSD; k++) ds[k] = FINF;
    {
        int W0 = g_nodeStart[g_cellArr[pt]] - 22;
        if (W0 < 0) W0 = 0;
        if (W0 > N_NODES - SEEDW) W0 = N_NODES - SEEDW;
        #pragma unroll 4
        for (int i = 0; i < SEEDW; i++) {
            float4 v = __ldg(&g_nodes4s[W0 + i]);
            float s = fmaf(qa, v.x, fmaf(qb, v.y, fmaf(qc, v.z, v.w)));
            INSERT20(s);
        }
    }
    // theta: per-lane upper bound, margin covers packed-key perturbation (<= |s|*2^-11)
    const float T0 = ds[KSD-1];
    const float theta = T0 + fabsf(T0) * 0.002f + 1e-5f;
    const unsigned thbits = __float_as_uint(theta);

    // ---- sweep chain initialized to theta (only keys < theta can enter) ----
    float d[KCH];
    #pragma unroll
    for (int k = 0; k < KCH; k++) d[k] = theta;
    // raw-s fire threshold: key(s) >= s - |s|*2^-11 >= s - 0.06 for |s| <= ~120
    float dthr = d[KCH-1] + 0.06f;

    // ---- single sweep, batch-16, raw-s min + one conservative vote per batch ----
    for (int ch = 0; ch < N_NODES / CHUNK; ch++) {
        const int base = ch * CHUNK;
        __syncthreads();
        #pragma unroll
        for (int i = tid; i < CHUNK; i += 128)
            sn[i] = g_nodes4s[base + i];
        __syncthreads();
        #pragma unroll 1
        for (int jj = 0; jj < CHUNK; jj += 16) {
            float sv[16];
            #pragma unroll
            for (int u = 0; u < 16; u++) {
                float4 v = sn[jj + u];
                sv[u] = fmaf(qa, v.x, fmaf(qb, v.y, fmaf(qc, v.z, v.w)));
            }
            float m01 = fminf(sv[0], sv[1]),   m23 = fminf(sv[2], sv[3]);
            float m45 = fminf(sv[4], sv[5]),   m67 = fminf(sv[6], sv[7]);
            float m89 = fminf(sv[8], sv[9]),   mab = fminf(sv[10], sv[11]);
            float mcd = fminf(sv[12], sv[13]), mef = fminf(sv[14], sv[15]);
            float smin = fminf(fminf(fminf(m01, m23), fminf(m45, m67)),
                               fminf(fminf(m89, mab), fminf(mcd, mef)));
            if (__any_sync(0xffffffffu, smin < dthr)) {
                #pragma unroll
                for (int u = 0; u < 16; u++) {
                    float key = pack_key(sv[u], base + jj + u);
                    if (__any_sync(0xffffffffu, key < d[KCH-1])) INSERT24(key);
                }
                dthr = d[KCH-1] + 0.06f;
            }
        }
    }

    // ---- exact re-selection: padding entries (== theta) act as +INF ----
    float m0 = -FINF, m1 = -FINF, m2 = -FINF, m3 = -FINF, m4 = -FINF;
    float smin2 = FINF;
    #pragma unroll
    for (int k = 0; k < KCH; k++) {
        unsigned kb = __float_as_uint(d[k]);
        int j = (int)(kb & 0xFFFu);
        float4 v = __ldg(&g_nodes4s[j]);
        float s = fmaf(qa, v.x, fmaf(qb, v.y, fmaf(qc, v.z, v.w)));
        s = (kb == thbits) ? FINF : s;
        smin2 = fminf(smin2, s);
        m4 = fmaxf(m4, fminf(m3, s));
        m3 = fmaxf(m3, fminf(m2, s));
        m2 = fmaxf(m2, fminf(m1, s));
        m1 = fmaxf(m1, fminf(m0, s));
        m0 = fmaxf(m0, s);
    }
    const float T = m4;
    const float dis0 = smin2 + pp;
    const float dismax = T + pp;
    const float rcpmax = 1.0f / dismax;

    // ---- blend over chain entries with s <= T (padding s = INF auto-excluded) ----
    float wsum = 0.0f, pb0 = 0.0f, pb1 = 0.0f, pb2 = 0.0f;
    float rb9[9];
    #pragma unroll
    for (int i = 0; i < 9; i++) rb9[i] = 0.0f;

    #pragma unroll 4
    for (int k = 0; k < KCH; k++) {
        unsigned kb = __float_as_uint(d[k]);
        int j = (int)(kb & 0xFFFu);
        float4 v = __ldg(&g_nodes4s[j]);
        float s = fmaf(qa, v.x, fmaf(qb, v.y, fmaf(qc, v.z, v.w)));
        s = (kb == thbits) ? FINF : s;
        if (s <= T) {
            float dis = s + pp;
            float uu = 1.0f - dis * rcpmax;
            float w = uu * uu;
            const float4* rec = g_rec_s + j * 4;
            float4 r0 = __ldg(rec + 0);
            float4 r1 = __ldg(rec + 1);
            float4 r2v = __ldg(rec + 2);
            float4 r3 = __ldg(rec + 3);
            float y0 = px - r2v.y, y1 = py - r2v.z, y2 = pz - r2v.w;
            float q0 = fmaf(r0.x, y0, fmaf(r0.w, y1, fmaf(r1.z, y2, r3.x)));
            float q1 = fmaf(r0.y, y0, fmaf(r1.x, y1, fmaf(r1.w, y2, r3.y)));
            float q2 = fmaf(r0.z, y0, fmaf(r1.y, y1, fmaf(r2v.x, y2, r3.z)));
            wsum += w;
            pb0 = fmaf(w, q0, pb0);
            pb1 = fmaf(w, q1, pb1);
            pb2 = fmaf(w, q2, pb2);
            rb9[0] = fmaf(w, r0.x, rb9[0]);
            rb9[1] = fmaf(w, r0.w, rb9[1]);
            rb9[2] = fmaf(w, r1.z, rb9[2]);
            rb9[3] = fmaf(w, r0.y, rb9[3]);
            rb9[4] = fmaf(w, r1.x, rb9[4]);
            rb9[5] = fmaf(w, r1.w, rb9[5]);
            rb9[6] = fmaf(w, r0.z, rb9[6]);
            rb9[7] = fmaf(w, r1.y, rb9[7]);
            rb9[8] = fmaf(w, r2v.x, rb9[8]);
        }
    }

    const float inv = 1.0f / wsum;
    float o0 = (dis0 > 0.00021f) ? 1000000000.0f : pb0 * inv;
    float* op = out + (long)pt * 3;
    op[0] = o0;
    op[1] = pb1 * inv;
    op[2] = pb2 * inv;
    float* orr = out + (long)N_PTS * 3 + (long)pt * 9;
    #pragma unroll
    for (int i = 0; i < 9; i++) orr[i] = rb9[i] * inv;
}

extern "C" void kernel_launch(void* const* d_in, const int* in_sizes, int n_in,
                              void* d_out, int out_size) {
    const float* inputs = (const float*)d_in[0];
    const float* vd     = (const float*)d_in[1];
    const float* R      = (const float*)d_in[2];
    const float* g      = (const float*)d_in[3];
    const float* t      = (const float*)d_in[4];
    float* out = (float*)d_out;

    zero_kernel<<<NBINS / 256, 256>>>();
    count_kernel<<<N_PTS / 256, 256>>>(inputs, vd);
    scan_kernel<<<2, 1024>>>();
    scatter_kernel<<<N_PTS / 256, 256>>>();
    build_sorted_kernel<<<N_NODES / 256, 256>>>(vd, R, g, t);
    dg_kernel<<<N_PTS / 128, 128>>>(inputs, out);
}

// round 13
// speedup vs baseline: 1.0460x; 1.0460x over previous
#include <cuda_runtime.h>

#define N_PTS 65536
#define N_NODES 4096
#define KCH 24            // sweep chain length per half (guard band over 20)
#define KSD 20
#define IN_STRIDE 35
#define NBINS 4096
#define CHUNK 2048
#define FINF 3.0e38f

__device__ float4 g_nodes4s[N_NODES];     // Morton-sorted: (vx,vy,vz,|v|^2)
__device__ float4 g_rec_s[N_NODES * 4];   // sorted records: R, g+t, g
__device__ int g_binCount[NBINS], g_binCursor[NBINS], g_cellArr[N_PTS], g_perm[N_PTS];
__device__ int g_nBinCount[NBINS], g_nBinCursor[NBINS], g_nodeStart[NBINS];
__device__ int g_nCell[N_NODES], g_nPerm[N_NODES];

__device__ __forceinline__ unsigned expand3(unsigned v) {
    return (v & 1u) | ((v & 2u) << 2) | ((v & 4u) << 4) | ((v & 8u) << 6);
}
__device__ __forceinline__ int quant4(float x) {
    int q = (int)floorf((x + 3.0f) * (16.0f / 6.0f));
    return q < 0 ? 0 : (q > 15 ? 15 : q);
}
__device__ __forceinline__ unsigned morton3(float x, float y, float z) {
    return expand3(quant4(x)) | (expand3(quant4(y)) << 1) | (expand3(quant4(z)) << 2);
}

__global__ void zero_kernel() {
    int i = blockIdx.x * blockDim.x + threadIdx.x;
    if (i < NBINS) { g_binCount[i] = 0; g_nBinCount[i] = 0; }
}

__global__ void count_kernel(const float* __restrict__ inputs, const float* __restrict__ vd) {
    int idx = blockIdx.x * blockDim.x + threadIdx.x;
    if (idx < N_PTS) {
        const float* pr = inputs + (long)idx * IN_STRIDE;
        unsigned code = morton3(pr[0], pr[1], pr[2]);
        g_cellArr[idx] = (int)code;
        atomicAdd(&g_binCount[code], 1);
    }
    if (idx < N_NODES) {
        unsigned code = morton3(vd[idx*3+0], vd[idx*3+1], vd[idx*3+2]);
        g_nCell[idx] = (int)code;
        atomicAdd(&g_nBinCount[code], 1);
    }
}

__global__ void scan_kernel() {
    __shared__ int ssum[1024];
    int tid = threadIdx.x;
    const int* cntArr = (blockIdx.x == 0) ? g_binCount : g_nBinCount;
    int base = tid * 4;
    int c0 = cntArr[base], c1 = cntArr[base+1], c2 = cntArr[base+2], c3 = cntArr[base+3];
    ssum[tid] = c0 + c1 + c2 + c3;
    __syncthreads();
    for (int off = 1; off < 1024; off <<= 1) {
        int v = ssum[tid];
        int add = (tid >= off) ? ssum[tid - off] : 0;
        __syncthreads();
        ssum[tid] = v + add;
        __syncthreads();
    }
    int excl = (tid > 0) ? ssum[tid - 1] : 0;
    int e0 = excl, e1 = excl + c0, e2 = excl + c0 + c1, e3 = excl + c0 + c1 + c2;
    if (blockIdx.x == 0) {
        g_binCursor[base] = e0; g_binCursor[base+1] = e1;
        g_binCursor[base+2] = e2; g_binCursor[base+3] = e3;
    } else {
        g_nBinCursor[base] = e0; g_nBinCursor[base+1] = e1;
        g_nBinCursor[base+2] = e2; g_nBinCursor[base+3] = e3;
        g_nodeStart[base] = e0; g_nodeStart[base+1] = e1;
        g_nodeStart[base+2] = e2; g_nodeStart[base+3] = e3;
    }
}

__global__ void scatter_kernel() {
    int idx = blockIdx.x * blockDim.x + threadIdx.x;
    if (idx < N_PTS) {
        int pos = atomicAdd(&g_binCursor[g_cellArr[idx]], 1);
        g_perm[pos] = idx;
    }
    if (idx < N_NODES) {
        int pos = atomicAdd(&g_nBinCursor[g_nCell[idx]], 1);
        g_nPerm[pos] = idx;
    }
}

__global__ void build_sorted_kernel(const float* __restrict__ vd, const float* __restrict__ R,
                                    const float* __restrict__ g, const float* __restrict__ t) {
    int pos = blockIdx.x * blockDim.x + threadIdx.x;
    if (pos >= N_NODES) return;
    int j = g_nPerm[pos];
    float vx = vd[j*3+0], vy = vd[j*3+1], vz = vd[j*3+2];
    g_nodes4s[pos] = make_float4(vx, vy, vz, fmaf(vx,vx,fmaf(vy,vy,vz*vz)));
    const float* Rj = R + j*9;
    float g0 = g[j*3+0], g1 = g[j*3+1], g2 = g[j*3+2];
    float gt0 = g0 + t[j*3+0], gt1 = g1 + t[j*3+1], gt2 = g2 + t[j*3+2];
    g_rec_s[pos*4+0] = make_float4(Rj[0], Rj[1], Rj[2], Rj[3]);
    g_rec_s[pos*4+1] = make_float4(Rj[4], Rj[5], Rj[6], Rj[7]);
    g_rec_s[pos*4+2] = make_float4(Rj[8], gt0, gt1, gt2);
    g_rec_s[pos*4+3] = make_float4(g0, g1, g2, 0.0f);
}

__device__ __forceinline__ float pack_key(float s, int j) {
    return __uint_as_float((__float_as_uint(s) & 0xFFFFF000u) | (unsigned)j);
}

#define INSERT24(SV) do {                                              \
    _Pragma("unroll")                                                  \
    for (int _k = KCH-1; _k >= 1; --_k)                                \
        d[_k] = fminf(d[_k], fmaxf(d[_k-1], (SV)));                    \
    d[0] = fminf(d[0], (SV));                                          \
} while (0)

#define INSERT20(SV) do {                                              \
    _Pragma("unroll")                                                  \
    for (int _k = KSD-1; _k >= 1; --_k)                                \
        ds[_k] = fminf(ds[_k], fmaxf(ds[_k-1], (SV)));                 \
    ds[0] = fminf(ds[0], (SV));                                        \
} while (0)

// 128 threads = 64 points; lane pairs (tid, tid^1) split the node range.
__global__ void __launch_bounds__(128) dg_kernel(const float* __restrict__ inputs,
                                                 float* __restrict__ out) {
    __shared__ float4 sn[CHUNK];   // 32 KB; reused as exact-s buffer afterwards

    const int tid = threadIdx.x;
    const int par = tid & 1;
    const int pt = g_perm[blockIdx.x * 64 + (tid >> 1)];
    const float* pr = inputs + (long)pt * IN_STRIDE;
    const float px = pr[0], py = pr[1], pz = pr[2];
    const float pp = fmaf(px, px, fmaf(py, py, pz * pz));
    const float qa = -2.0f * px, qb = -2.0f * py, qc = -2.0f * pz;

    // ---- seed: each pair lane runs a 20-chain over its own 32-node half-window ----
    float ds[KSD];
    #pragma unroll
    for (int k = 0; k < KSD; k++) ds[k] = FINF;
    {
        int W0 = g_nodeStart[g_cellArr[pt]] - 22;
        if (W0 < 0) W0 = 0;
        if (W0 > N_NODES - 64) W0 = N_NODES - 64;
        const int b0 = W0 + par * 32;
        #pragma unroll 4
        for (int i = 0; i < 32; i++) {
            float4 v = __ldg(&g_nodes4s[b0 + i]);
            float s = fmaf(qa, v.x, fmaf(qb, v.y, fmaf(qc, v.z, v.w)));
            INSERT20(s);
        }
    }
    // theta: min of the two half-window 20ths (each >= T_true); pair-identical
    float thMine = ds[KSD-1];
    float thPeer = __shfl_xor_sync(0xffffffffu, thMine, 1);
    const float T0 = fminf(thMine, thPeer);
    const float theta = T0 + fabsf(T0) * 0.002f + 1e-5f;
    const unsigned thbits = __float_as_uint(theta);

    // ---- sweep chain (per half) initialized to theta ----
    float d[KCH];
    #pragma unroll
    for (int k = 0; k < KCH; k++) d[k] = theta;

    // ---- sweep: each lane covers stride-2-interleaved batch slots of each 16-node run ----
    for (int ch = 0; ch < N_NODES / CHUNK; ch++) {
        const int base = ch * CHUNK;
        __syncthreads();
        #pragma unroll
        for (int i = tid; i < CHUNK; i += 128)
            sn[i] = g_nodes4s[base + i];
        __syncthreads();
        #pragma unroll 1
        for (int jj = 0; jj < CHUNK; jj += 16) {
            float kk[8];
            #pragma unroll
            for (int u = 0; u < 8; u++) {
                int off = jj + 2 * u + par;
                float4 v = sn[off];
                float s = fmaf(qa, v.x, fmaf(qb, v.y, fmaf(qc, v.z, v.w)));
                kk[u] = pack_key(s, base + off);
            }
            float kmin = fminf(fminf(fminf(kk[0], kk[1]), fminf(kk[2], kk[3])),
                               fminf(fminf(kk[4], kk[5]), fminf(kk[6], kk[7])));
            if (__any_sync(0xffffffffu, kmin < d[KCH-1])) {
                #pragma unroll
                for (int u = 0; u < 8; u++) {
                    if (__any_sync(0xffffffffu, kk[u] < d[KCH-1])) INSERT24(kk[u]);
                }
            }
        }
    }

    // ---- re-selection: exact s for own 24 entries -> smem; 20-chain over union 48 ----
    __syncthreads();                       // all warps done with sn as chunk
    float* s_ex = (float*)sn;              // 24*128*4 = 12 KB <= 32 KB

    float smin2 = FINF;
    #pragma unroll
    for (int k = 0; k < KSD; k++) ds[k] = FINF;
    #pragma unroll
    for (int k = 0; k < KCH; k++) {
        unsigned kb = __float_as_uint(d[k]);
        int j = (int)(kb & 0xFFFu);
        float4 v = __ldg(&g_nodes4s[j]);
        float s = fmaf(qa, v.x, fmaf(qb, v.y, fmaf(qc, v.z, v.w)));
        s = (kb == thbits) ? FINF : s;
        s_ex[k * 128 + tid] = s;
        smin2 = fminf(smin2, s);
        INSERT20(s);
    }
    __syncwarp();
    // insert partner's 24 exact values -> ds[19] = exact 20th of union
    #pragma unroll
    for (int k = 0; k < KCH; k++) {
        float s = s_ex[k * 128 + (tid ^ 1)];
        INSERT20(s);
    }
    const float T = ds[KSD-1];
    smin2 = fminf(smin2, __shfl_xor_sync(0xffffffffu, smin2, 1));
    const float dis0 = smin2 + pp;
    const float dismax = T + pp;
    const float rcpmax = 1.0f / dismax;

    // ---- blend own 24 entries with s <= T (s from smem; padding INF auto-excluded) ----
    float wsum = 0.0f, pb0 = 0.0f, pb1 = 0.0f, pb2 = 0.0f;
    float rb9[9];
    #pragma unroll
    for (int i = 0; i < 9; i++) rb9[i] = 0.0f;

    #pragma unroll 4
    for (int k = 0; k < KCH; k++) {
        float s = s_ex[k * 128 + tid];
        if (s <= T) {
            int j = (int)(__float_as_uint(d[k]) & 0xFFFu);
            float dis = s + pp;
            float uu = 1.0f - dis * rcpmax;
            float w = uu * uu;
            const float4* rec = g_rec_s + j * 4;
            float4 r0 = __ldg(rec + 0);
            float4 r1 = __ldg(rec + 1);
            float4 r2v = __ldg(rec + 2);
            float4 r3 = __ldg(rec + 3);
            float y0 = px - r2v.y, y1 = py - r2v.z, y2 = pz - r2v.w;
            float q0 = fmaf(r0.x, y0, fmaf(r0.w, y1, fmaf(r1.z, y2, r3.x)));
            float q1 = fmaf(r0.y, y0, fmaf(r1.x, y1, fmaf(r1.w, y2, r3.y)));
            float q2 = fmaf(r0.z, y0, fmaf(r1.y, y1, fmaf(r2v.x, y2, r3.z)));
            wsum += w;
            pb0 = fmaf(w, q0, pb0);
            pb1 = fmaf(w, q1, pb1);
            pb2 = fmaf(w, q2, pb2);
            rb9[0] = fmaf(w, r0.x, rb9[0]);
            rb9[1] = fmaf(w, r0.w, rb9[1]);
            rb9[2] = fmaf(w, r1.z, rb9[2]);
            rb9[3] = fmaf(w, r0.y, rb9[3]);
            rb9[4] = fmaf(w, r1.x, rb9[4]);
            rb9[5] = fmaf(w, r1.w, rb9[5]);
            rb9[6] = fmaf(w, r0.z, rb9[6]);
            rb9[7] = fmaf(w, r1.y, rb9[7]);
            rb9[8] = fmaf(w, r2v.x, rb9[8]);
        }
    }

    // ---- pair-sum accumulators ----
    wsum += __shfl_xor_sync(0xffffffffu, wsum, 1);
    pb0  += __shfl_xor_sync(0xffffffffu, pb0, 1);
    pb1  += __shfl_xor_sync(0xffffffffu, pb1, 1);
    pb2  += __shfl_xor_sync(0xffffffffu, pb2, 1);
    #pragma unroll
    for (int i = 0; i < 9; i++)
        rb9[i] += __shfl_xor_sync(0xffffffffu, rb9[i], 1);

    const float inv = 1.0f / wsum;
    if (par == 0) {
        float o0 = (dis0 > 0.00021f) ? 1000000000.0f : pb0 * inv;
        float* op = out + (long)pt * 3;
        op[0] = o0;
        op[1] = pb1 * inv;
        op[2] = pb2 * inv;
    } else {
        float* orr = out + (long)N_PTS * 3 + (long)pt * 9;
        #pragma unroll
        for (int i = 0; i < 9; i++) orr[i] = rb9[i] * inv;
    }
}

extern "C" void kernel_launch(void* const* d_in, const int* in_sizes, int n_in,
                              void* d_out, int out_size) {
    const float* inputs = (const float*)d_in[0];
    const float* vd     = (const float*)d_in[1];
    const float* R      = (const float*)d_in[2];
    const float* g      = (const float*)d_in[3];
    const float* t      = (const float*)d_in[4];
    float* out = (float*)d_out;

    zero_kernel<<<NBINS / 256, 256>>>();
    count_kernel<<<N_PTS / 256, 256>>>(inputs, vd);
    scan_kernel<<<2, 1024>>>();
    scatter_kernel<<<N_PTS / 256, 256>>>();
    build_sorted_kernel<<<N_NODES / 256, 256>>>(vd, R, g, t);
    dg_kernel<<<N_PTS / 64, 128>>>(inputs, out);
}